// round 7
// baseline (speedup 1.0000x reference)
#include <cuda_runtime.h>
#include <cstdint>
#include <cstddef>

// ---------------------------------------------------------------------------
// Problem dims (fixed by the dataset)
// ---------------------------------------------------------------------------
#define B_DIM 16384
#define C_DIM 1000
#define D_DIM 1024
#define CPAD  1024   // padded K / leading dim everywhere

// GEMM tiling
#define BM 128
#define BN 128
#define BK 32
#define KT (CPAD / BK)     // 32
#define STAGES 3
#define NTH 256

#define LDSTR 36                               // smem row stride (floats)
// 144B row stride => ldmatrix's 8 rows land on 8 distinct 16B banks: conflict-free
#define TILE_FLOATS (128 * LDSTR)              // one operand tile
#define STAGE_FLOATS (2 * TILE_FLOATS)
#define STAGE_BYTES (STAGE_FLOATS * 4)
#define SMEM_BYTES (STAGES * STAGE_BYTES)      // 110592 -> 2 CTAs/SM

// ---------------------------------------------------------------------------
// Device scratch (no allocation allowed). Zero-initialized at load; padding
// columns [1000,1024) of intermediates are never written -> stay 0.
// ---------------------------------------------------------------------------
__device__ float g_xrnd [(size_t)B_DIM * CPAD];   // tf32-rounded x
__device__ float g_wp   [(size_t)C_DIM * CPAD];   // tf32-rounded Wp
__device__ float g_adj1 [(size_t)C_DIM * CPAD];   // rn(adj[c,k] * w1[k]), k-padded
__device__ float g_adj2 [(size_t)C_DIM * CPAD];
__device__ float g_xinit[(size_t)B_DIM * CPAD];   // tf32-rounded x@Wp^T+bp
__device__ float g_out1 [(size_t)B_DIM * CPAD];   // tf32-rounded relu(gcn1)

// ---------------------------------------------------------------------------
// PTX helpers (all sm_80/sm_90-era — compile for plain sm_100)
// ---------------------------------------------------------------------------
__device__ __forceinline__ uint32_t su32(const void* p) {
    uint32_t a;
    asm("{ .reg .u64 t; cvta.to.shared.u64 t, %1; cvt.u32.u64 %0, t; }"
        : "=r"(a) : "l"(p));
    return a;
}
__device__ __forceinline__ float rn_tf32(float x) {
    uint32_t r;
    asm("cvt.rn.tf32.f32 %0, %1;" : "=r"(r) : "f"(x));
    return __uint_as_float(r);
}
__device__ __forceinline__ void cpasync16(uint32_t dst, const void* src) {
    asm volatile("cp.async.cg.shared.global [%0], [%1], 16;"
                 :: "r"(dst), "l"(src));
}
// zero-fill variant: src-size 0 -> 16 bytes of zeros written
__device__ __forceinline__ void cpasync16z(uint32_t dst, const void* src,
                                           bool valid) {
    int sz = valid ? 16 : 0;
    asm volatile("cp.async.cg.shared.global [%0], [%1], 16, %2;"
                 :: "r"(dst), "l"(src), "r"(sz));
}
#define CP_COMMIT() asm volatile("cp.async.commit_group;")
#define CP_WAIT(n)  asm volatile("cp.async.wait_group %0;" :: "n"(n))

__device__ __forceinline__ void ldsm4(uint32_t* r, uint32_t addr) {
    asm volatile("ldmatrix.sync.aligned.m8n8.x4.shared.b16 {%0,%1,%2,%3}, [%4];"
                 : "=r"(r[0]), "=r"(r[1]), "=r"(r[2]), "=r"(r[3])
                 : "r"(addr));
}

__device__ __forceinline__ void mma16n8k8(float* c, const uint32_t* a,
                                          uint32_t b0, uint32_t b1) {
    asm volatile(
        "mma.sync.aligned.m16n8k8.row.col.f32.tf32.tf32.f32 "
        "{%0,%1,%2,%3}, {%4,%5,%6,%7}, {%8,%9}, {%0,%1,%2,%3};\n"
        : "+f"(c[0]), "+f"(c[1]), "+f"(c[2]), "+f"(c[3])
        : "r"(a[0]), "r"(a[1]), "r"(a[2]), "r"(a[3]), "r"(b0), "r"(b1));
}

// ---------------------------------------------------------------------------
// Prep kernels
// ---------------------------------------------------------------------------
__global__ void round_copy_kernel(const float* __restrict__ src,
                                  float* __restrict__ dst, int n4) {
    int i = blockIdx.x * blockDim.x + threadIdx.x;
    if (i < n4) {
        float4 v = reinterpret_cast<const float4*>(src)[i];
        v.x = rn_tf32(v.x); v.y = rn_tf32(v.y);
        v.z = rn_tf32(v.z); v.w = rn_tf32(v.w);
        reinterpret_cast<float4*>(dst)[i] = v;
    }
}

__global__ void prep_adj_kernel(const float* __restrict__ adj,
                                const float* __restrict__ hw1,
                                const float* __restrict__ hw2) {
    int k = blockIdx.x * blockDim.x + threadIdx.x;   // 0..1023
    int c = blockIdx.y;                              // 0..999
    float a1 = 0.f, a2 = 0.f;
    if (k < C_DIM) {
        float av = adj[(size_t)c * C_DIM + k];
        float w1 = (hw1[k] + hw1[C_DIM + k] + hw1[2 * C_DIM + k]) * (1.f / 3.f);
        float w2 = (hw2[k] + hw2[C_DIM + k] + hw2[2 * C_DIM + k]) * (1.f / 3.f);
        a1 = rn_tf32(av * w1);
        a2 = rn_tf32(av * w2);
    }
    g_adj1[(size_t)c * CPAD + k] = a1;
    g_adj2[(size_t)c * CPAD + k] = a2;
}

// ---------------------------------------------------------------------------
// Fused tf32 mma.sync GEMM:  D[m,n] = sum_k A[m,k] * B[n,k]
//   MODE 0: +bias, round->Cout (ld CPAD)
//   MODE 1: relu, round->Cout  (ld CPAD)
//   MODE 2: Cout = resid + 0.5*acc (ld C_DIM, final output)
// lda = ldb = CPAD for all modes, K = CPAD.
// ---------------------------------------------------------------------------
__device__ __forceinline__ void load_tile(
    uint32_t sm0, const float* __restrict__ A, const float* __restrict__ Bm,
    int m0, int n0, int kt, int tid)
{
    const int slot = kt % STAGES;
    const uint32_t sA = sm0 + slot * STAGE_BYTES;
    const uint32_t sB = sA + TILE_FLOATS * 4;
    const int k0 = kt * BK;
    const int r  = tid >> 3;          // 0..31
    const int kl = (tid & 7) * 4;     // 0,4,...,28

#pragma unroll
    for (int p = 0; p < 4; p++) {
        const int row = p * 32 + r;
        cpasync16(sA + (uint32_t)(row * LDSTR + kl) * 4,
                  A + (size_t)(m0 + row) * CPAD + k0 + kl);
    }
#pragma unroll
    for (int p = 0; p < 4; p++) {
        const int row = p * 32 + r;
        const int n = n0 + row;
        const int nc = (n < C_DIM) ? n : (C_DIM - 1);   // clamp src addr
        cpasync16z(sB + (uint32_t)(row * LDSTR + kl) * 4,
                   Bm + (size_t)nc * CPAD + k0 + kl, n < C_DIM);
    }
}

template <int MODE>
__global__ void __launch_bounds__(NTH, 2)
gemm_tc(const float* __restrict__ A, const float* __restrict__ Bm,
        const float* __restrict__ bias, const float* __restrict__ resid,
        float* __restrict__ Cout)
{
    extern __shared__ float smem[];
    const uint32_t sm0 = su32(smem);

    const int tid  = threadIdx.x;
    const int warp = tid >> 5;
    const int lane = tid & 31;
    const int g = lane >> 2;          // groupID 0..7
    const int t = lane & 3;           // thread-in-group 0..3
    const int wm = (warp >> 2) * 64;  // warp M offset (0 or 64)
    const int wn = (warp & 3) * 32;   // warp N offset (0,32,64,96)

    const int m0 = blockIdx.y * BM;
    const int n0 = blockIdx.x * BN;

    // ldmatrix per-thread row addressing: matrix id = lane>>3, row = lane&7.
    const int mi  = lane >> 3;
    const int rid = lane & 7;
    // A x4 tiles: [m+0..7,k0..3][m+8..15,k0..3][m+0..7,k4..7][m+8..15,k4..7]
    const uint32_t aoff =
        (uint32_t)(((wm + (mi & 1) * 8 + rid) * LDSTR + (mi >> 1) * 4) * 4);
    // B x4 tiles: [n+0..7,k0..3][n+0..7,k4..7][n+8..15,k0..3][n+8..15,k4..7]
    const uint32_t boff = (uint32_t)(TILE_FLOATS * 4) +
        (uint32_t)(((wn + (mi >> 1) * 8 + rid) * LDSTR + (mi & 1) * 4) * 4);

    float acc[4][4][4];
#pragma unroll
    for (int i = 0; i < 4; i++)
#pragma unroll
        for (int j = 0; j < 4; j++)
#pragma unroll
            for (int c = 0; c < 4; c++) acc[i][j][c] = 0.f;

    // prologue: fill STAGES-1 stages
#pragma unroll
    for (int kt = 0; kt < STAGES - 1; kt++) {
        load_tile(sm0, A, Bm, m0, n0, kt, tid);
        CP_COMMIT();
    }

    // double-buffered fragment registers
    uint32_t a[2][4][4], b[2][2][4];

    for (int kt = 0; kt < KT; kt++) {
        CP_WAIT(STAGES - 2);
        __syncthreads();

        const int kn = kt + STAGES - 1;
        if (kn < KT) load_tile(sm0, A, Bm, m0, n0, kn, tid);
        CP_COMMIT();

        const int slot = kt % STAGES;
        const uint32_t sbase = sm0 + slot * STAGE_BYTES;

        // load ks=0 fragments into buffer 0
#pragma unroll
        for (int i = 0; i < 4; i++)
            ldsm4(a[0][i], sbase + aoff + (uint32_t)(i * 16 * LDSTR * 4));
#pragma unroll
        for (int jj = 0; jj < 2; jj++)
            ldsm4(b[0][jj], sbase + boff + (uint32_t)(jj * 16 * LDSTR * 4));

#pragma unroll
        for (int ks = 0; ks < 4; ks++) {
            const int cur = ks & 1, nxt = cur ^ 1;
            // prefetch ks+1 fragments while MMAs for ks run
            if (ks < 3) {
                const uint32_t kb = (uint32_t)((ks + 1) * 32);
#pragma unroll
                for (int i = 0; i < 4; i++)
                    ldsm4(a[nxt][i],
                          sbase + aoff + (uint32_t)(i * 16 * LDSTR * 4) + kb);
#pragma unroll
                for (int jj = 0; jj < 2; jj++)
                    ldsm4(b[nxt][jj],
                          sbase + boff + (uint32_t)(jj * 16 * LDSTR * 4) + kb);
            }
            // b[x][jj] regs: [n_lo k_lo][n_lo k_hi][n_hi k_lo][n_hi k_hi]
#pragma unroll
            for (int i = 0; i < 4; i++)
#pragma unroll
                for (int j = 0; j < 4; j++)
                    mma16n8k8(acc[i][j], a[cur][i],
                              b[cur][j >> 1][(j & 1) * 2],
                              b[cur][j >> 1][(j & 1) * 2 + 1]);
        }
    }

    // epilogue: per-thread float2 stores
#pragma unroll
    for (int i = 0; i < 4; i++) {
        const int mr0 = m0 + wm + i * 16 + g;       // rows mr0 and mr0+8
#pragma unroll
        for (int j = 0; j < 4; j++) {
            const int n = n0 + wn + j * 8 + t * 2;
            if (n < C_DIM) {
                float c0 = acc[i][j][0], c1 = acc[i][j][1];
                float c2 = acc[i][j][2], c3 = acc[i][j][3];
                if (MODE == 0) {
                    const float b0 = bias[n], b1 = bias[n + 1];
                    c0 = rn_tf32(c0 + b0); c1 = rn_tf32(c1 + b1);
                    c2 = rn_tf32(c2 + b0); c3 = rn_tf32(c3 + b1);
                } else if (MODE == 1) {
                    c0 = rn_tf32(fmaxf(c0, 0.f)); c1 = rn_tf32(fmaxf(c1, 0.f));
                    c2 = rn_tf32(fmaxf(c2, 0.f)); c3 = rn_tf32(fmaxf(c3, 0.f));
                }
                if (MODE == 2) {
                    float2 r0 = *reinterpret_cast<const float2*>(
                        resid + (size_t)mr0 * CPAD + n);
                    float2 r1 = *reinterpret_cast<const float2*>(
                        resid + (size_t)(mr0 + 8) * CPAD + n);
                    float2 v0 = make_float2(r0.x + 0.5f * c0, r0.y + 0.5f * c1);
                    float2 v1 = make_float2(r1.x + 0.5f * c2, r1.y + 0.5f * c3);
                    *reinterpret_cast<float2*>(
                        Cout + (size_t)mr0 * C_DIM + n) = v0;
                    *reinterpret_cast<float2*>(
                        Cout + (size_t)(mr0 + 8) * C_DIM + n) = v1;
                } else {
                    *reinterpret_cast<float2*>(
                        Cout + (size_t)mr0 * CPAD + n) = make_float2(c0, c1);
                    *reinterpret_cast<float2*>(
                        Cout + (size_t)(mr0 + 8) * CPAD + n) = make_float2(c2, c3);
                }
            }
        }
    }
}

// ---------------------------------------------------------------------------
// Launch: inputs per metadata order: x, adj, Wp, bp, hw1, hw2
// ---------------------------------------------------------------------------
extern "C" void kernel_launch(void* const* d_in, const int* in_sizes, int n_in,
                              void* d_out, int out_size) {
    const float* x   = (const float*)d_in[0];
    const float* adj = (const float*)d_in[1];
    const float* Wp  = (const float*)d_in[2];
    const float* bp  = (const float*)d_in[3];
    const float* hw1 = (const float*)d_in[4];
    const float* hw2 = (const float*)d_in[5];
    float* out = (float*)d_out;

    float *p_xrnd, *p_wp, *p_adj1, *p_adj2, *p_xinit, *p_out1;
    cudaGetSymbolAddress((void**)&p_xrnd,  g_xrnd);
    cudaGetSymbolAddress((void**)&p_wp,    g_wp);
    cudaGetSymbolAddress((void**)&p_adj1,  g_adj1);
    cudaGetSymbolAddress((void**)&p_adj2,  g_adj2);
    cudaGetSymbolAddress((void**)&p_xinit, g_xinit);
    cudaGetSymbolAddress((void**)&p_out1,  g_out1);

    cudaFuncSetAttribute(gemm_tc<0>,
        cudaFuncAttributeMaxDynamicSharedMemorySize, SMEM_BYTES);
    cudaFuncSetAttribute(gemm_tc<1>,
        cudaFuncAttributeMaxDynamicSharedMemorySize, SMEM_BYTES);
    cudaFuncSetAttribute(gemm_tc<2>,
        cudaFuncAttributeMaxDynamicSharedMemorySize, SMEM_BYTES);

    // prep: tf32-round x, Wp; prescale+round adj by head means
    {
        int n4 = (B_DIM * D_DIM) / 4;
        round_copy_kernel<<<(n4 + 255) / 256, 256>>>(x, p_xrnd, n4);
        int w4 = (C_DIM * D_DIM) / 4;
        round_copy_kernel<<<(w4 + 255) / 256, 256>>>(Wp, p_wp, w4);
        dim3 g(CPAD / 256, C_DIM);
        prep_adj_kernel<<<g, 256>>>(adj, hw1, hw2);
    }

    dim3 grid((C_DIM + BN - 1) / BN, B_DIM / BM);  // (8, 128)
    dim3 block(NTH);

    gemm_tc<0><<<grid, block, SMEM_BYTES>>>(p_xrnd, p_wp, bp, nullptr, p_xinit);
    gemm_tc<1><<<grid, block, SMEM_BYTES>>>(p_xinit, p_adj1, nullptr, nullptr, p_out1);
    gemm_tc<2><<<grid, block, SMEM_BYTES>>>(p_out1, p_adj2, nullptr, p_xinit, out);
}

// round 8
// speedup vs baseline: 1.7814x; 1.7814x over previous
#include <cuda_runtime.h>
#include <cuda_fp16.h>
#include <cstdint>
#include <cstddef>

// ---------------------------------------------------------------------------
// Problem dims (fixed by the dataset)
// ---------------------------------------------------------------------------
#define B_DIM 16384
#define C_DIM 1000
#define D_DIM 1024
#define CPAD  1024   // padded K / leading dim everywhere

// GEMM tiling (fp16 m16n8k16)
#define BM 128
#define BN 128
#define BK 64              // fp16 elements per k-tile = 128 bytes per row
#define KT (CPAD / BK)     // 16
#define STAGES 3
#define NTH 256

#define LDSTR_H 72                              // smem row stride in fp16 (144 B)
// 144B stride => ldmatrix's 8 rows hit 8 distinct 16B banks: conflict-free
#define TILE_BYTES (128 * LDSTR_H * 2)          // 18432
#define STAGE_BYTES (2 * TILE_BYTES)            // 36864
#define SMEM_BYTES (STAGES * STAGE_BYTES)       // 110592 -> 2 CTAs/SM

// ---------------------------------------------------------------------------
// Device scratch (no allocation allowed). Zero-initialized at load; padding
// columns [1000,1024) of fp16 intermediates are never written -> stay 0.
// ---------------------------------------------------------------------------
__device__ __half g_xh   [(size_t)B_DIM * CPAD];   // fp16(x)
__device__ __half g_wph  [(size_t)C_DIM * CPAD];   // fp16(Wp)
__device__ __half g_adj1 [(size_t)C_DIM * CPAD];   // fp16(adj*w1), k-padded 0
__device__ __half g_adj2 [(size_t)C_DIM * CPAD];
__device__ __half g_xinit_h[(size_t)B_DIM * CPAD]; // fp16(x@Wp^T+bp)
__device__ float  g_xinit_f[(size_t)B_DIM * CPAD]; // f32 copy for residual
__device__ __half g_out1_h [(size_t)B_DIM * CPAD]; // fp16(relu(gcn1))

// ---------------------------------------------------------------------------
// PTX helpers (sm_80-era; legal for plain sm_100)
// ---------------------------------------------------------------------------
__device__ __forceinline__ uint32_t su32(const void* p) {
    uint32_t a;
    asm("{ .reg .u64 t; cvta.to.shared.u64 t, %1; cvt.u32.u64 %0, t; }"
        : "=r"(a) : "l"(p));
    return a;
}
__device__ __forceinline__ void cpasync16(uint32_t dst, const void* src) {
    asm volatile("cp.async.cg.shared.global [%0], [%1], 16;"
                 :: "r"(dst), "l"(src));
}
__device__ __forceinline__ void cpasync16z(uint32_t dst, const void* src,
                                           bool valid) {
    int sz = valid ? 16 : 0;
    asm volatile("cp.async.cg.shared.global [%0], [%1], 16, %2;"
                 :: "r"(dst), "l"(src), "r"(sz));
}
#define CP_COMMIT() asm volatile("cp.async.commit_group;")
#define CP_WAIT(n)  asm volatile("cp.async.wait_group %0;" :: "n"(n))

__device__ __forceinline__ void ldsm4(uint32_t* r, uint32_t addr) {
    asm volatile("ldmatrix.sync.aligned.m8n8.x4.shared.b16 {%0,%1,%2,%3}, [%4];"
                 : "=r"(r[0]), "=r"(r[1]), "=r"(r[2]), "=r"(r[3])
                 : "r"(addr));
}

__device__ __forceinline__ void mma16816(float* c, const uint32_t* a,
                                         uint32_t b0, uint32_t b1) {
    asm volatile(
        "mma.sync.aligned.m16n8k16.row.col.f32.f16.f16.f32 "
        "{%0,%1,%2,%3}, {%4,%5,%6,%7}, {%8,%9}, {%0,%1,%2,%3};\n"
        : "+f"(c[0]), "+f"(c[1]), "+f"(c[2]), "+f"(c[3])
        : "r"(a[0]), "r"(a[1]), "r"(a[2]), "r"(a[3]), "r"(b0), "r"(b1));
}

// ---------------------------------------------------------------------------
// Prep kernels
// ---------------------------------------------------------------------------
__global__ void conv_half_kernel(const float* __restrict__ src,
                                 __half* __restrict__ dst, int n4) {
    int i = blockIdx.x * blockDim.x + threadIdx.x;
    if (i < n4) {
        float4 v = reinterpret_cast<const float4*>(src)[i];
        __half2 h0 = __floats2half2_rn(v.x, v.y);
        __half2 h1 = __floats2half2_rn(v.z, v.w);
        uint2 u;
        u.x = *reinterpret_cast<uint32_t*>(&h0);
        u.y = *reinterpret_cast<uint32_t*>(&h1);
        reinterpret_cast<uint2*>(dst)[i] = u;
    }
}

__global__ void prep_adj_kernel(const float* __restrict__ adj,
                                const float* __restrict__ hw1,
                                const float* __restrict__ hw2) {
    int k = blockIdx.x * blockDim.x + threadIdx.x;   // 0..1023
    int c = blockIdx.y;                              // 0..999
    float a1 = 0.f, a2 = 0.f;
    if (k < C_DIM) {
        float av = adj[(size_t)c * C_DIM + k];
        float w1 = (hw1[k] + hw1[C_DIM + k] + hw1[2 * C_DIM + k]) * (1.f / 3.f);
        float w2 = (hw2[k] + hw2[C_DIM + k] + hw2[2 * C_DIM + k]) * (1.f / 3.f);
        a1 = av * w1;
        a2 = av * w2;
    }
    g_adj1[(size_t)c * CPAD + k] = __float2half_rn(a1);
    g_adj2[(size_t)c * CPAD + k] = __float2half_rn(a2);
}

// ---------------------------------------------------------------------------
// Fused fp16 mma.sync GEMM:  D[m,n] = sum_k A[m,k] * B[n,k]  (fp16 in, f32 acc)
//   MODE 0: +bias -> fp16 CoutH AND f32 CoutF       (ld CPAD)
//   MODE 1: relu  -> fp16 CoutH                     (ld CPAD)
//   MODE 2: CoutF = resid + 0.5*acc                 (ld C_DIM, final output)
// ---------------------------------------------------------------------------
__device__ __forceinline__ void load_tile(
    uint32_t sm0, const __half* __restrict__ A, const __half* __restrict__ Bm,
    int m0, int n0, int kt, int tid)
{
    const int slot = kt % STAGES;
    const uint32_t sA = sm0 + slot * STAGE_BYTES;
    const uint32_t sB = sA + TILE_BYTES;
    const int k0 = kt * BK;
    const int r  = tid >> 3;          // 0..31
    const int kl = (tid & 7) * 8;     // fp16 element offset (16B chunks)

#pragma unroll
    for (int p = 0; p < 4; p++) {
        const int row = p * 32 + r;
        cpasync16(sA + (uint32_t)(row * LDSTR_H + kl) * 2,
                  A + (size_t)(m0 + row) * CPAD + k0 + kl);
    }
#pragma unroll
    for (int p = 0; p < 4; p++) {
        const int row = p * 32 + r;
        const int n = n0 + row;
        const int nc = (n < C_DIM) ? n : (C_DIM - 1);   // clamp src addr
        cpasync16z(sB + (uint32_t)(row * LDSTR_H + kl) * 2,
                   Bm + (size_t)nc * CPAD + k0 + kl, n < C_DIM);
    }
}

template <int MODE>
__global__ void __launch_bounds__(NTH, 2)
gemm_tc(const __half* __restrict__ A, const __half* __restrict__ Bm,
        const float* __restrict__ bias, const float* __restrict__ resid,
        float* __restrict__ CoutF, __half* __restrict__ CoutH)
{
    extern __shared__ char smem[];
    const uint32_t sm0 = su32(smem);

    const int tid  = threadIdx.x;
    const int warp = tid >> 5;
    const int lane = tid & 31;
    const int g = lane >> 2;          // groupID 0..7
    const int t = lane & 3;           // thread-in-group 0..3
    const int wm = (warp >> 2) * 64;  // warp M offset (0 or 64)
    const int wn = (warp & 3) * 32;   // warp N offset (0,32,64,96)

    const int m0 = blockIdx.y * BM;
    const int n0 = blockIdx.x * BN;

    // ldmatrix per-thread row addressing: matrix id = lane>>3, row = lane&7.
    const int mi  = lane >> 3;
    const int rid = lane & 7;
    // A x4 tiles: [m_lo,k_lo][m_hi,k_lo][m_lo,k_hi][m_hi,k_hi] (k halves of 8)
    const uint32_t aoff =
        (uint32_t)(((wm + (mi & 1) * 8 + rid) * LDSTR_H + (mi >> 1) * 8) * 2);
    // B x4 tiles: [n_lo,k_lo][n_lo,k_hi][n_hi,k_lo][n_hi,k_hi]
    const uint32_t boff = (uint32_t)TILE_BYTES +
        (uint32_t)(((wn + (mi >> 1) * 8 + rid) * LDSTR_H + (mi & 1) * 8) * 2);

    float acc[4][4][4];
#pragma unroll
    for (int i = 0; i < 4; i++)
#pragma unroll
        for (int j = 0; j < 4; j++)
#pragma unroll
            for (int c = 0; c < 4; c++) acc[i][j][c] = 0.f;

    // prologue: fill STAGES-1 stages
#pragma unroll
    for (int kt = 0; kt < STAGES - 1; kt++) {
        load_tile(sm0, A, Bm, m0, n0, kt, tid);
        CP_COMMIT();
    }

    for (int kt = 0; kt < KT; kt++) {
        CP_WAIT(STAGES - 2);
        __syncthreads();

        const int kn = kt + STAGES - 1;
        if (kn < KT) load_tile(sm0, A, Bm, m0, n0, kn, tid);
        CP_COMMIT();

        const int slot = kt % STAGES;
        const uint32_t sbase = sm0 + slot * STAGE_BYTES;

#pragma unroll
        for (int ks = 0; ks < 4; ks++) {           // 4 x k16 steps per 64-k tile
            const uint32_t kb = (uint32_t)(ks * 32);   // 16 fp16 = 32 bytes
            uint32_t a[4][4], b[2][4];
#pragma unroll
            for (int i = 0; i < 4; i++)
                ldsm4(a[i], sbase + aoff + (uint32_t)(i * 16 * LDSTR_H * 2) + kb);
#pragma unroll
            for (int jj = 0; jj < 2; jj++)
                ldsm4(b[jj], sbase + boff + (uint32_t)(jj * 16 * LDSTR_H * 2) + kb);
            // b[jj] regs: [n_lo b0][n_lo b1][n_hi b0][n_hi b1]
#pragma unroll
            for (int i = 0; i < 4; i++)
#pragma unroll
                for (int j = 0; j < 4; j++)
                    mma16816(acc[i][j], a[i],
                             b[j >> 1][(j & 1) * 2], b[j >> 1][(j & 1) * 2 + 1]);
        }
    }

    // epilogue
#pragma unroll
    for (int i = 0; i < 4; i++) {
        const int mr0 = m0 + wm + i * 16 + g;       // rows mr0 and mr0+8
#pragma unroll
        for (int j = 0; j < 4; j++) {
            const int n = n0 + wn + j * 8 + t * 2;
            if (n < C_DIM) {
                float c0 = acc[i][j][0], c1 = acc[i][j][1];
                float c2 = acc[i][j][2], c3 = acc[i][j][3];
                if (MODE == 0) {
                    const float b0 = bias[n], b1 = bias[n + 1];
                    c0 += b0; c1 += b1; c2 += b0; c3 += b1;
                    __half2 h0 = __floats2half2_rn(c0, c1);
                    __half2 h1 = __floats2half2_rn(c2, c3);
                    *reinterpret_cast<__half2*>(
                        CoutH + (size_t)mr0 * CPAD + n) = h0;
                    *reinterpret_cast<__half2*>(
                        CoutH + (size_t)(mr0 + 8) * CPAD + n) = h1;
                    *reinterpret_cast<float2*>(
                        CoutF + (size_t)mr0 * CPAD + n) = make_float2(c0, c1);
                    *reinterpret_cast<float2*>(
                        CoutF + (size_t)(mr0 + 8) * CPAD + n) = make_float2(c2, c3);
                } else if (MODE == 1) {
                    c0 = fmaxf(c0, 0.f); c1 = fmaxf(c1, 0.f);
                    c2 = fmaxf(c2, 0.f); c3 = fmaxf(c3, 0.f);
                    __half2 h0 = __floats2half2_rn(c0, c1);
                    __half2 h1 = __floats2half2_rn(c2, c3);
                    *reinterpret_cast<__half2*>(
                        CoutH + (size_t)mr0 * CPAD + n) = h0;
                    *reinterpret_cast<__half2*>(
                        CoutH + (size_t)(mr0 + 8) * CPAD + n) = h1;
                } else {
                    float2 r0 = *reinterpret_cast<const float2*>(
                        resid + (size_t)mr0 * CPAD + n);
                    float2 r1 = *reinterpret_cast<const float2*>(
                        resid + (size_t)(mr0 + 8) * CPAD + n);
                    float2 v0 = make_float2(r0.x + 0.5f * c0, r0.y + 0.5f * c1);
                    float2 v1 = make_float2(r1.x + 0.5f * c2, r1.y + 0.5f * c3);
                    *reinterpret_cast<float2*>(
                        CoutF + (size_t)mr0 * C_DIM + n) = v0;
                    *reinterpret_cast<float2*>(
                        CoutF + (size_t)(mr0 + 8) * C_DIM + n) = v1;
                }
            }
        }
    }
}

// ---------------------------------------------------------------------------
// Launch: inputs per metadata order: x, adj, Wp, bp, hw1, hw2
// ---------------------------------------------------------------------------
extern "C" void kernel_launch(void* const* d_in, const int* in_sizes, int n_in,
                              void* d_out, int out_size) {
    const float* x   = (const float*)d_in[0];
    const float* adj = (const float*)d_in[1];
    const float* Wp  = (const float*)d_in[2];
    const float* bp  = (const float*)d_in[3];
    const float* hw1 = (const float*)d_in[4];
    const float* hw2 = (const float*)d_in[5];
    float* out = (float*)d_out;

    __half *p_xh, *p_wph, *p_adj1, *p_adj2, *p_xinit_h, *p_out1_h;
    float *p_xinit_f;
    cudaGetSymbolAddress((void**)&p_xh,      g_xh);
    cudaGetSymbolAddress((void**)&p_wph,     g_wph);
    cudaGetSymbolAddress((void**)&p_adj1,    g_adj1);
    cudaGetSymbolAddress((void**)&p_adj2,    g_adj2);
    cudaGetSymbolAddress((void**)&p_xinit_h, g_xinit_h);
    cudaGetSymbolAddress((void**)&p_xinit_f, g_xinit_f);
    cudaGetSymbolAddress((void**)&p_out1_h,  g_out1_h);

    cudaFuncSetAttribute(gemm_tc<0>,
        cudaFuncAttributeMaxDynamicSharedMemorySize, SMEM_BYTES);
    cudaFuncSetAttribute(gemm_tc<1>,
        cudaFuncAttributeMaxDynamicSharedMemorySize, SMEM_BYTES);
    cudaFuncSetAttribute(gemm_tc<2>,
        cudaFuncAttributeMaxDynamicSharedMemorySize, SMEM_BYTES);

    // prep: convert x, Wp to fp16; prescale adj by head means -> fp16
    {
        int n4 = (B_DIM * D_DIM) / 4;
        conv_half_kernel<<<(n4 + 255) / 256, 256>>>(x, p_xh, n4);
        int w4 = (C_DIM * D_DIM) / 4;
        conv_half_kernel<<<(w4 + 255) / 256, 256>>>(Wp, p_wph, w4);
        dim3 g(CPAD / 256, C_DIM);
        prep_adj_kernel<<<g, 256>>>(adj, hw1, hw2);
    }

    dim3 grid((C_DIM + BN - 1) / BN, B_DIM / BM);  // (8, 128)
    dim3 block(NTH);

    gemm_tc<0><<<grid, block, SMEM_BYTES>>>(p_xh, p_wph, bp, nullptr,
                                            p_xinit_f, p_xinit_h);
    gemm_tc<1><<<grid, block, SMEM_BYTES>>>(p_xinit_h, p_adj1, nullptr, nullptr,
                                            nullptr, p_out1_h);
    gemm_tc<2><<<grid, block, SMEM_BYTES>>>(p_out1_h, p_adj2, nullptr, p_xinit_f,
                                            out, nullptr);
}